// round 7
// baseline (speedup 1.0000x reference)
#include <cuda_runtime.h>
#include <cstdint>
#include <cstddef>

#define BB 1024
#define TT 1024
#define NN 34
#define BPB 2                      // batches per block (forward)
#define FWD_THREADS (BPB * NN)     // 68 threads
#define FWD_BLOCKS  (BB / BPB)     // 512 CTAs — exact, no duplicate batches

// Backpointers u8 [b][t][j]; final argmax per batch.
__device__ unsigned char g_bp[(size_t)BB * TT * NN];
__device__ int g_idx[BB];

__device__ __forceinline__ unsigned long long addx2(unsigned long long a, unsigned long long b) {
    unsigned long long r;
    asm("add.rn.f32x2 %0, %1, %2;" : "=l"(r) : "l"(a), "l"(b));
    return r;
}
__device__ __forceinline__ unsigned long long packff(float f) {
    unsigned long long r; unsigned u = __float_as_uint(f);
    asm("mov.b64 %0, {%1, %1};" : "=l"(r) : "r"(u));
    return r;
}
__device__ __forceinline__ void unpk(unsigned long long v, float& lo, float& hi) {
    unsigned a, b;
    asm("mov.b64 {%0, %1}, %2;" : "=r"(a), "=r"(b) : "l"(v));
    lo = __uint_as_float(a); hi = __uint_as_float(b);
}

__global__ __launch_bounds__(FWD_THREADS)
void viterbi_fwd(const float* __restrict__ feat,
                 const float* __restrict__ trans,
                 float* __restrict__ out)
{
    const int tid = threadIdx.x;
    const int bl  = tid / NN;
    const int j   = tid % NN;
    const int b   = blockIdx.x * BPB + bl;     // always < BB

    __shared__ __align__(16) float sc[2][BPB][36];
    __shared__ float tend[NN];
    __shared__ float fin[BPB][NN];

    // transition row j packed as f32x2 pairs
    unsigned long long trp[17];
#pragma unroll
    for (int i = 0; i < 17; i++) {
        unsigned lo = __float_as_uint(trans[j * NN + 2 * i]);
        unsigned hi = __float_as_uint(trans[j * NN + 2 * i + 1]);
        asm("mov.b64 %0, {%1, %2};" : "=l"(trp[i]) : "r"(lo), "r"(hi));
    }
    if (tid < NN) tend[tid] = trans[(NN - 1) * NN + tid];

    const float init = (j == NN - 2) ? 0.0f : -6969.0f;
    sc[0][bl][j] = init;
    __syncthreads();

    const size_t fbase = (size_t)b * ((size_t)TT * NN) + j;
    const float* fp = feat + fbase;
    unsigned char* bpp = g_bp + (size_t)b * ((size_t)TT * NN) + j;

    // 4-deep feat prefetch ring
    float fring[4];
#pragma unroll
    for (int u = 0; u < 4; u++) fring[u] = __ldg(fp + (size_t)u * NN);
    fp += (size_t)4 * NN;

    int cur = 0;
#pragma unroll 1
    for (int tb = 0; tb < TT; tb += 4) {
#pragma unroll
        for (int u = 0; u < 4; u++) {
            const int t = tb + u;
            float f = fring[u];
            float fn = 0.0f;
            if (t + 4 < TT) fn = __ldg(fp);
            fp += NN;
            fring[u] = fn;

            const ulonglong2* sp2 = (const ulonglong2*)&sc[cur][bl][0];
            unsigned long long ff = packff(f);

            // candidates c[k] = (score[k] + f) + tr[j][k]  (XLA association)
            float c[NN];
#pragma unroll
            for (int i = 0; i < 8; i++) {
                ulonglong2 q = sp2[i];
                unsigned long long v0 = addx2(addx2(q.x, ff), trp[2 * i]);
                unsigned long long v1 = addx2(addx2(q.y, ff), trp[2 * i + 1]);
                unpk(v0, c[4 * i], c[4 * i + 1]);
                unpk(v1, c[4 * i + 2], c[4 * i + 3]);
            }
            {
                unsigned long long q = *(const unsigned long long*)&sc[cur][bl][32];
                unsigned long long v = addx2(addx2(q, ff), trp[16]);
                unpk(v, c[32], c[33]);
            }

            // exact max tree on a working copy (keeps c[] alive for the bp scan)
            float w[NN];
#pragma unroll
            for (int k = 0; k < NN; k++) w[k] = c[k];
#pragma unroll
            for (int s = 1; s < NN; s <<= 1)
#pragma unroll
                for (int k = 0; k + s < NN; k += (s << 1))
                    w[k] = fmaxf(w[k], w[k + s]);
            const float m0 = w[0];

            // critical chain: publish new score, then barrier
            sc[cur ^ 1][bl][j] = m0;
            cur ^= 1;
            __syncthreads();

            // off-chain (after barrier, registers only): smallest k with c[k]==m0.
            // Parallel pair-selects + min tree — no serial SEL chain.
            int e[17];
#pragma unroll
            for (int i = 0; i < 17; i++) {
                int lo = (c[2 * i]     == m0) ? (2 * i)     : 63;
                int hi = (c[2 * i + 1] == m0) ? (2 * i + 1) : 63;
                e[i] = lo < hi ? lo : hi;
            }
#pragma unroll
            for (int s = 1; s < 17; s <<= 1)
#pragma unroll
                for (int k = 0; k + s < 17; k += (s << 1))
                    e[k] = e[k] < e[k + s] ? e[k] : e[k + s];

            *bpp = (unsigned char)e[0];
            bpp += NN;
        }
    }

    fin[bl][j] = sc[cur][bl][j] + tend[j];
    __syncthreads();
    if (j == 0) {
        float bm = -3.4e38f; int bi = 0;
#pragma unroll
        for (int k = 0; k < NN; k++) {
            float v = fin[bl][k];
            if (v > bm) { bm = v; bi = k; }
        }
        out[b] = bm;
        g_idx[b] = bi;
    }
}

// Proven chase: stage batch's bp table in smem, thread 0 walks it (~48 us).
__global__ __launch_bounds__(256)
void viterbi_back(float* __restrict__ out)
{
    __shared__ unsigned char bp[TT * NN];    // 34816 B
    const int b = blockIdx.x;

    const uint4* src = (const uint4*)(g_bp + (size_t)b * ((size_t)TT * NN));
    uint4* dst = (uint4*)bp;
    for (int i = threadIdx.x; i < (TT * NN) / 16; i += 256) dst[i] = src[i];
    __syncthreads();

    if (threadIdx.x == 0) {
        int i = g_idx[b];
        float* path = out + BB + (size_t)b * (TT + 1);
        path[TT] = (float)i;
        for (int t = TT - 1; t >= 0; t--) {
            i = bp[t * NN + i];
            path[t] = (float)i;
        }
    }
}

extern "C" void kernel_launch(void* const* d_in, const int* in_sizes, int n_in,
                              void* d_out, int out_size)
{
    const float* feat  = (const float*)d_in[0];
    const float* trans = (const float*)d_in[1];
    if (n_in >= 2 && in_sizes[0] == NN * NN) {
        feat  = (const float*)d_in[1];
        trans = (const float*)d_in[0];
    }
    float* out = (float*)d_out;

    viterbi_fwd<<<FWD_BLOCKS, FWD_THREADS>>>(feat, trans, out);
    viterbi_back<<<BB, 256>>>(out);
}